// round 9
// baseline (speedup 1.0000x reference)
#include <cuda_runtime.h>
#include <cfloat>

// Shapes (fixed by the problem)
#define BQ 8
#define NQ 16384
#define DQ 768
#define CQ 8
#define NCQ 2

#define THREADS 256
#define WARPS_PER_BLOCK 8
#define BPB 512                                   // blocks per batch
#define GRID (BQ * BPB)                           // 4096
#define WARPS_PER_BATCH (BPB * WARPS_PER_BLOCK)   // 4096
#define ROWS_PER_WARP (NQ / WARPS_PER_BATCH)      // 4
#define NSTEP (ROWS_PER_WARP * 2)                 // 8 half-row pipeline steps

// Scratch per (batch, cluster): [dot_w0_sum, dot_w1_sum, count].
// Zero at module load; the finalizing block re-zeros it each replay.
__device__ float        g_accum[BQ * CQ * 3];
__device__ unsigned int g_ticket;

__global__ __launch_bounds__(THREADS, 4) void fused_kernel(
    const float* __restrict__ x,      // [B, N, D]
    const int*   __restrict__ labels, // [B, N]
    const float* __restrict__ w,      // [NC, D]
    const float* __restrict__ hb,     // [NC]
    float*       __restrict__ out)    // [B, NC]
{
    __shared__ float4 s_w0[6 * 32];   // head_w row 0, chunk layout [k*32 + lane]
    __shared__ float4 s_w1[6 * 32];   // head_w row 1
    __shared__ float  s_bins[CQ * 3];
    __shared__ int    s_last;

    const int tid  = threadIdx.x;
    const int lane = tid & 31;
    const int warp = tid >> 5;

    if (tid < CQ * 3) s_bins[tid] = 0.0f;
    {   // stage head_w into shared (chunk layout matches per-lane x loads)
        const float4* w0v = reinterpret_cast<const float4*>(w);
        const float4* w1v = reinterpret_cast<const float4*>(w + DQ);
        if (tid < 192) { s_w0[tid] = w0v[tid]; s_w1[tid] = w1v[tid]; }
    }
    __syncthreads();

    const int b         = blockIdx.x / BPB;
    const int warp_in_b = (blockIdx.x % BPB) * WARPS_PER_BLOCK + warp;
    const long base     = (long)b * NQ;

    // Per-thread per-cluster dot accumulators; count lives in ONE register:
    // lane i (i<8) counts rows of cluster i.
    float acc0[CQ], acc1[CQ];
    #pragma unroll
    for (int i = 0; i < CQ; i++) { acc0[i] = 0.0f; acc1[i] = 0.0f; }
    int my_cnt = 0;

    // Half-row double-buffered pipeline.
    // step s: row = s>>1, half = s&1. Buffer parity = s&1 alternates per step.
    float4 buf[2][3];
    int    lab[2];
    float  d0 = 0.0f, d1 = 0.0f;

    #define LOADSTEP(bi, s)                                                      \
        do {                                                                     \
            const int _row  = warp_in_b + ((s) >> 1) * WARPS_PER_BATCH;          \
            const int _half = (s) & 1;                                           \
            const float4* _xv =                                                  \
                reinterpret_cast<const float4*>(x + (base + _row) * (long)DQ)    \
                + _half * 96;                                                    \
            _Pragma("unroll")                                                    \
            for (int _k = 0; _k < 3; _k++)                                       \
                buf[bi][_k] = __ldcs(_xv + lane + 32 * _k);                      \
            if (_half == 0) lab[((s) >> 1) & 1] = labels[base + _row];           \
        } while (0)

    LOADSTEP(0, 0);
    #pragma unroll
    for (int s = 0; s < NSTEP; s++) {
        const int bi = s & 1;
        if (s + 1 < NSTEP) LOADSTEP((s + 1) & 1, s + 1);

        const int half = s & 1;
        #pragma unroll
        for (int k = 0; k < 3; k++) {
            const float4 vv = buf[bi][k];
            const float4 w0 = s_w0[(half * 3 + k) * 32 + lane];
            const float4 w1 = s_w1[(half * 3 + k) * 32 + lane];
            d0 = fmaf(vv.x, w0.x, d0); d0 = fmaf(vv.y, w0.y, d0);
            d0 = fmaf(vv.z, w0.z, d0); d0 = fmaf(vv.w, w0.w, d0);
            d1 = fmaf(vv.x, w1.x, d1); d1 = fmaf(vv.y, w1.y, d1);
            d1 = fmaf(vv.z, w1.z, d1); d1 = fmaf(vv.w, w1.w, d1);
        }

        if (half == 1) {               // row complete: bank it
            const int c = lab[(s >> 1) & 1];
            #pragma unroll
            for (int i = 0; i < CQ; i++) {
                if (c == i) { acc0[i] += d0; acc1[i] += d1; }
            }
            if (lane == c) my_cnt++;
            d0 = 0.0f; d1 = 0.0f;
        }
    }
    #undef LOADSTEP

    // Per-warp tree reduction of the 8 cluster sums (off the critical path).
    #pragma unroll
    for (int i = 0; i < CQ; i++) {
        #pragma unroll
        for (int off = 16; off > 0; off >>= 1) {
            acc0[i] += __shfl_down_sync(0xffffffffu, acc0[i], off);
            acc1[i] += __shfl_down_sync(0xffffffffu, acc1[i], off);
        }
    }
    if (lane == 0) {
        #pragma unroll
        for (int i = 0; i < CQ; i++) {
            atomicAdd(&s_bins[i * 3 + 0], acc0[i]);
            atomicAdd(&s_bins[i * 3 + 1], acc1[i]);
        }
    }
    if (lane < CQ && my_cnt > 0)
        atomicAdd(&s_bins[lane * 3 + 2], (float)my_cnt);
    __syncthreads();

    if (tid < CQ * 3) atomicAdd(&g_accum[b * CQ * 3 + tid], s_bins[tid]);
    __threadfence();   // order this block's global atomics before the ticket
    __syncthreads();

    if (tid == 0) {
        unsigned t = atomicAdd(&g_ticket, 1u);
        s_last = (t == (unsigned)(GRID - 1)) ? 1 : 0;
    }
    __syncthreads();
    if (!s_last) return;

    // ---- last block: finalize ----
    __threadfence();
    float bl0 = 0.0f, bl1 = 0.0f;
    const bool isb = (tid < BQ);
    if (isb) {
        const float b0 = hb[0], b1 = hb[1];
        float best = -FLT_MAX;
        #pragma unroll
        for (int c = 0; c < CQ; c++) {
            const float s0 = __ldcg(&g_accum[(tid * CQ + c) * 3 + 0]);
            const float s1 = __ldcg(&g_accum[(tid * CQ + c) * 3 + 1]);
            const float cn = __ldcg(&g_accum[(tid * CQ + c) * 3 + 2]);
            const float inv = 1.0f / fmaxf(cn, 1.0f);
            const float l0 = s0 * inv + b0;
            const float l1 = s1 * inv + b1;
            // NC=2: 1 - softmax(l)[0] = sigmoid(l1 - l0), monotone in (l1 - l0).
            const float score = l1 - l0;
            if (score > best) { best = score; bl0 = l0; bl1 = l1; }
        }
    }
    __syncthreads();   // all reads of g_accum done before reset
    if (tid < BQ * CQ * 3) g_accum[tid] = 0.0f;   // self-reset for next replay
    if (tid == 0) g_ticket = 0u;
    if (isb) {
        out[tid * NCQ + 0] = bl0;
        out[tid * NCQ + 1] = bl1;
    }
}

extern "C" void kernel_launch(void* const* d_in, const int* in_sizes, int n_in,
                              void* d_out, int out_size)
{
    const float* x      = (const float*)d_in[0]; // inst_feat [8,16384,768] f32
    const int*   labels = (const int*)  d_in[1]; // [8,16384] i32
    const float* w      = (const float*)d_in[2]; // head_w [2,768] f32
    const float* hb     = (const float*)d_in[3]; // head_b [2] f32
    float* out = (float*)d_out;                  // [8,2] f32

    fused_kernel<<<GRID, THREADS>>>(x, labels, w, hb, out);
}

// round 10
// speedup vs baseline: 1.1175x; 1.1175x over previous
#include <cuda_runtime.h>
#include <cfloat>
#include <cstdint>

// Shapes (fixed by the problem)
#define BQ 8
#define NQ 16384
#define DQ 768
#define CQ 8
#define NCQ 2

#define THREADS 256
#define NWARP 8
#define NSTAGE 4
#define STAGE_ROWS 8
#define STAGE_BYTES (STAGE_ROWS * DQ * 4)        // 24576
#define STAGE_F4 (STAGE_ROWS * DQ / 4)           // 1536 float4 per stage
#define ROW_F4 (DQ / 4)                          // 192 float4 per row

#define GRID 304                                 // 2 blocks x 152 SMs, one wave
#define TOTAL_STAGES ((BQ * NQ) / STAGE_ROWS)    // 16384
#define QS (TOTAL_STAGES / GRID)                 // 53
#define RS (TOTAL_STAGES - QS * GRID)            // 272
#define STAGES_PER_BATCH (NQ / STAGE_ROWS)       // 2048

// Scratch per (batch, cluster): [dot_w0_sum, dot_w1_sum, count].
// Zero at module load; the finalizing block re-zeros it each replay.
__device__ float        g_accum[BQ * CQ * 3];
__device__ unsigned int g_ticket;

// ---- mbarrier / bulk-copy PTX helpers ----
__device__ __forceinline__ unsigned smem_u32(const void* p) {
    return (unsigned)__cvta_generic_to_shared(p);
}
__device__ __forceinline__ void mbar_init(unsigned a, unsigned cnt) {
    asm volatile("mbarrier.init.shared::cta.b64 [%0], %1;" :: "r"(a), "r"(cnt) : "memory");
}
__device__ __forceinline__ void mbar_expect_tx(unsigned a, unsigned bytes) {
    asm volatile("mbarrier.arrive.expect_tx.shared::cta.b64 _, [%0], %1;"
                 :: "r"(a), "r"(bytes) : "memory");
}
__device__ __forceinline__ void mbar_arrive(unsigned a) {
    asm volatile("mbarrier.arrive.shared::cta.b64 _, [%0];" :: "r"(a) : "memory");
}
__device__ __forceinline__ void mbar_wait(unsigned a, unsigned parity) {
    asm volatile(
        "{\n\t.reg .pred P;\n"
        "W%=:\n\tmbarrier.try_wait.parity.shared::cta.b64 P, [%0], %1, 0x989680;\n"
        "\t@P bra D%=;\n\tbra W%=;\nD%=:\n\t}"
        :: "r"(a), "r"(parity) : "memory");
}
__device__ __forceinline__ void bulk_g2s(unsigned dst, const void* src,
                                         unsigned bytes, unsigned bar) {
    asm volatile(
        "cp.async.bulk.shared::cta.global.mbarrier::complete_tx::bytes "
        "[%0], [%1], %2, [%3];"
        :: "r"(dst), "l"(src), "r"(bytes), "r"(bar) : "memory");
}

__global__ __launch_bounds__(THREADS, 2) void fused_kernel(
    const float* __restrict__ x,      // [B, N, D]
    const int*   __restrict__ labels, // [B, N]
    const float* __restrict__ w,      // [NC, D]
    const float* __restrict__ hb,     // [NC]
    float*       __restrict__ out)    // [B, NC]
{
    extern __shared__ float4 s_x[];          // NSTAGE * 24KB ring
    __shared__ float s_bins[BQ * CQ * 3];    // global-segment bins
    __shared__ int   s_last;
    __shared__ __align__(8) unsigned long long s_full[NSTAGE], s_empty[NSTAGE];

    const int tid  = threadIdx.x;
    const int lane = tid & 31;
    const int warp = tid >> 5;
    const int bid  = blockIdx.x;

    if (tid < BQ * CQ * 3) s_bins[tid] = 0.0f;
    unsigned full_b[NSTAGE], empty_b[NSTAGE];
    #pragma unroll
    for (int s = 0; s < NSTAGE; s++) {
        full_b[s]  = smem_u32(&s_full[s]);
        empty_b[s] = smem_u32(&s_empty[s]);
    }
    if (tid == 0) {
        #pragma unroll
        for (int s = 0; s < NSTAGE; s++) {
            mbar_init(full_b[s], 1);        // producer expect_tx + TMA completion
            mbar_init(empty_b[s], THREADS); // all threads arrive after consuming
        }
    }
    const unsigned sx_base = smem_u32(s_x);
    __syncthreads();

    // head_w in registers: lane l owns float4 chunks {l + 32k}, k = 0..5.
    float4 w0[6], w1[6];
    {
        const float4* w0v = reinterpret_cast<const float4*>(w);
        const float4* w1v = reinterpret_cast<const float4*>(w + DQ);
        #pragma unroll
        for (int k = 0; k < 6; k++) {
            w0[k] = w0v[lane + 32 * k];
            w1[k] = w1v[lane + 32 * k];
        }
    }

    // Balanced contiguous stage range for this block.
    const int n_it  = QS + (bid < RS ? 1 : 0);
    const int start = bid * QS + (bid < RS ? bid : RS);

    // Per-thread per-cluster accumulators; lane i (i<8) counts cluster-i rows.
    float acc0[CQ], acc1[CQ];
    #pragma unroll
    for (int i = 0; i < CQ; i++) { acc0[i] = 0.0f; acc1[i] = 0.0f; }
    int my_cnt = 0;
    int cur_b  = start / STAGES_PER_BATCH;

    // Prologue: fill the ring (n_it >= 53 > NSTAGE always).
    if (tid == 0) {
        #pragma unroll
        for (int j = 0; j < NSTAGE; j++) {
            mbar_expect_tx(full_b[j], STAGE_BYTES);
            bulk_g2s(sx_base + j * STAGE_BYTES,
                     x + (size_t)(start + j) * STAGE_ROWS * DQ,
                     STAGE_BYTES, full_b[j]);
        }
    }

    #define FLUSH_WARP(bb)                                                       \
        do {                                                                     \
            _Pragma("unroll")                                                    \
            for (int _i = 0; _i < CQ; _i++) {                                    \
                _Pragma("unroll")                                                \
                for (int _o = 16; _o > 0; _o >>= 1) {                            \
                    acc0[_i] += __shfl_down_sync(0xffffffffu, acc0[_i], _o);     \
                    acc1[_i] += __shfl_down_sync(0xffffffffu, acc1[_i], _o);     \
                }                                                                \
            }                                                                    \
            if (lane == 0) {                                                     \
                _Pragma("unroll")                                                \
                for (int _i = 0; _i < CQ; _i++) {                                \
                    atomicAdd(&s_bins[((bb) * CQ + _i) * 3 + 0], acc0[_i]);      \
                    atomicAdd(&s_bins[((bb) * CQ + _i) * 3 + 1], acc1[_i]);      \
                }                                                                \
            }                                                                    \
            if (lane < CQ && my_cnt > 0)                                         \
                atomicAdd(&s_bins[((bb) * CQ + lane) * 3 + 2], (float)my_cnt);   \
            _Pragma("unroll")                                                    \
            for (int _i = 0; _i < CQ; _i++) { acc0[_i] = 0.0f; acc1[_i] = 0.0f; }\
            my_cnt = 0;                                                          \
        } while (0)

    for (int it = 0; it < n_it; it++) {
        const int slot  = it & (NSTAGE - 1);
        const int stage = start + it;
        const int b     = stage / STAGES_PER_BATCH;   // block-uniform
        if (b != cur_b) { FLUSH_WARP(cur_b); cur_b = b; }

        const int row = stage * STAGE_ROWS + warp;    // this warp's row
        const int c   = labels[row];                  // warp-uniform broadcast

        mbar_wait(full_b[slot], (unsigned)((it >> 2) & 1));

        const float4* rp = s_x + slot * STAGE_F4 + warp * ROW_F4;
        float d0 = 0.0f, d1 = 0.0f;
        #pragma unroll
        for (int k = 0; k < 6; k++) {
            const float4 vv = rp[lane + 32 * k];      // conflict-free LDS.128
            d0 = fmaf(vv.x, w0[k].x, d0); d0 = fmaf(vv.y, w0[k].y, d0);
            d0 = fmaf(vv.z, w0[k].z, d0); d0 = fmaf(vv.w, w0[k].w, d0);
            d1 = fmaf(vv.x, w1[k].x, d1); d1 = fmaf(vv.y, w1[k].y, d1);
            d1 = fmaf(vv.z, w1[k].z, d1); d1 = fmaf(vv.w, w1[k].w, d1);
        }
        #pragma unroll
        for (int i = 0; i < CQ; i++) {
            if (c == i) { acc0[i] += d0; acc1[i] += d1; }
        }
        if (lane == c) my_cnt++;

        mbar_arrive(empty_b[slot]);                   // done reading this slot

        if (tid == 0 && it + NSTAGE < n_it) {
            const int jt = it + NSTAGE;               // same slot as `slot`
            mbar_wait(empty_b[slot], (unsigned)(((jt >> 2) + 1) & 1));
            mbar_expect_tx(full_b[slot], STAGE_BYTES);
            bulk_g2s(sx_base + slot * STAGE_BYTES,
                     x + (size_t)(start + jt) * STAGE_ROWS * DQ,
                     STAGE_BYTES, full_b[slot]);
        }
    }
    FLUSH_WARP(cur_b);
    #undef FLUSH_WARP

    __syncthreads();
    if (tid < BQ * CQ * 3) atomicAdd(&g_accum[tid], s_bins[tid]);
    __threadfence();   // order this block's global atomics before the ticket
    __syncthreads();

    if (tid == 0) {
        unsigned t = atomicAdd(&g_ticket, 1u);
        s_last = (t == (unsigned)(GRID - 1)) ? 1 : 0;
    }
    __syncthreads();
    if (!s_last) return;

    // ---- last block: finalize ----
    __threadfence();
    float bl0 = 0.0f, bl1 = 0.0f;
    const bool isb = (tid < BQ);
    if (isb) {
        const float b0 = hb[0], b1 = hb[1];
        float best = -FLT_MAX;
        #pragma unroll
        for (int c = 0; c < CQ; c++) {
            const float s0 = __ldcg(&g_accum[(tid * CQ + c) * 3 + 0]);
            const float s1 = __ldcg(&g_accum[(tid * CQ + c) * 3 + 1]);
            const float cn = __ldcg(&g_accum[(tid * CQ + c) * 3 + 2]);
            const float inv = 1.0f / fmaxf(cn, 1.0f);
            const float l0 = s0 * inv + b0;
            const float l1 = s1 * inv + b1;
            // NC=2: 1 - softmax(l)[0] = sigmoid(l1 - l0), monotone in (l1 - l0).
            const float score = l1 - l0;
            if (score > best) { best = score; bl0 = l0; bl1 = l1; }
        }
    }
    __syncthreads();   // all reads of g_accum done before reset
    if (tid < BQ * CQ * 3) g_accum[tid] = 0.0f;   // self-reset for next replay
    if (tid == 0) g_ticket = 0u;
    if (isb) {
        out[tid * NCQ + 0] = bl0;
        out[tid * NCQ + 1] = bl1;
    }
}

extern "C" void kernel_launch(void* const* d_in, const int* in_sizes, int n_in,
                              void* d_out, int out_size)
{
    const float* x      = (const float*)d_in[0]; // inst_feat [8,16384,768] f32
    const int*   labels = (const int*)  d_in[1]; // [8,16384] i32
    const float* w      = (const float*)d_in[2]; // head_w [2,768] f32
    const float* hb     = (const float*)d_in[3]; // head_b [2] f32
    float* out = (float*)d_out;                  // [8,2] f32

    cudaFuncSetAttribute(fused_kernel,
                         cudaFuncAttributeMaxDynamicSharedMemorySize,
                         NSTAGE * STAGE_BYTES);
    fused_kernel<<<GRID, THREADS, NSTAGE * STAGE_BYTES>>>(x, labels, w, hb, out);
}

// round 12
// speedup vs baseline: 1.1250x; 1.0067x over previous
#include <cuda_runtime.h>
#include <cfloat>
#include <cstdint>

// Shapes (fixed by the problem)
#define BQ 8
#define NQ 16384
#define DQ 768
#define CQ 8
#define NCQ 2

#define THREADS 256
#define NWARP 8
#define NSTAGE 4
#define STAGE_ROWS 8
#define STAGE_BYTES (STAGE_ROWS * DQ * 4)        // 24576
#define STAGE_F4 (STAGE_ROWS * DQ / 4)           // 1536 float4 per stage
#define ROW_F4 (DQ / 4)                          // 192 float4 per row

#define GRID 304                                 // 2 blocks x 152 SMs, one wave
#define TOTAL_STAGES ((BQ * NQ) / STAGE_ROWS)    // 16384
#define QS (TOTAL_STAGES / GRID)                 // 53
#define RS (TOTAL_STAGES - QS * GRID)            // 272
#define STAGES_PER_BATCH (NQ / STAGE_ROWS)       // 2048

// Scratch per (batch, cluster): [dot_w0_sum, dot_w1_sum, count].
// Zero at module load; the finalizing block re-zeros it each replay.
__device__ float        g_accum[BQ * CQ * 3];
__device__ unsigned int g_ticket;

// ---- mbarrier / bulk-copy PTX helpers ----
__device__ __forceinline__ unsigned smem_u32(const void* p) {
    return (unsigned)__cvta_generic_to_shared(p);
}
__device__ __forceinline__ void mbar_init(unsigned a, unsigned cnt) {
    asm volatile("mbarrier.init.shared::cta.b64 [%0], %1;" :: "r"(a), "r"(cnt) : "memory");
}
__device__ __forceinline__ void mbar_expect_tx(unsigned a, unsigned bytes) {
    asm volatile("mbarrier.arrive.expect_tx.shared::cta.b64 _, [%0], %1;"
                 :: "r"(a), "r"(bytes) : "memory");
}
__device__ __forceinline__ void mbar_arrive(unsigned a) {
    asm volatile("mbarrier.arrive.shared::cta.b64 _, [%0];" :: "r"(a) : "memory");
}
__device__ __forceinline__ void mbar_wait(unsigned a, unsigned parity) {
    asm volatile(
        "{\n\t.reg .pred P;\n"
        "W%=:\n\tmbarrier.try_wait.parity.shared::cta.b64 P, [%0], %1, 0x989680;\n"
        "\t@P bra D%=;\n\tbra W%=;\nD%=:\n\t}"
        :: "r"(a), "r"(parity) : "memory");
}
__device__ __forceinline__ void bulk_g2s(unsigned dst, const void* src,
                                         unsigned bytes, unsigned bar) {
    asm volatile(
        "cp.async.bulk.shared::cta.global.mbarrier::complete_tx::bytes "
        "[%0], [%1], %2, [%3];"
        :: "r"(dst), "l"(src), "r"(bytes), "r"(bar) : "memory");
}

__global__ __launch_bounds__(THREADS, 2) void fused_kernel(
    const float* __restrict__ x,      // [B, N, D]
    const int*   __restrict__ labels, // [B, N]
    const float* __restrict__ w,      // [NC, D]
    const float* __restrict__ hb,     // [NC]
    float*       __restrict__ out)    // [B, NC]
{
    extern __shared__ float4 s_x[];          // NSTAGE * 24KB ring
    __shared__ float s_bins[BQ * CQ * 3];    // global-segment bins
    __shared__ int   s_last;
    __shared__ __align__(8) unsigned long long s_full[NSTAGE], s_empty[NSTAGE];

    const int tid  = threadIdx.x;
    const int lane = tid & 31;
    const int warp = tid >> 5;
    const int bid  = blockIdx.x;

    if (tid < BQ * CQ * 3) s_bins[tid] = 0.0f;
    unsigned full_b[NSTAGE], empty_b[NSTAGE];
    #pragma unroll
    for (int s = 0; s < NSTAGE; s++) {
        full_b[s]  = smem_u32(&s_full[s]);
        empty_b[s] = smem_u32(&s_empty[s]);
    }
    if (tid == 0) {
        #pragma unroll
        for (int s = 0; s < NSTAGE; s++) {
            mbar_init(full_b[s], 1);        // producer expect_tx + TMA completion
            mbar_init(empty_b[s], THREADS); // all threads arrive after consuming
        }
    }
    const unsigned sx_base = smem_u32(s_x);
    __syncthreads();

    // head_w in registers: lane l owns float4 chunks {l + 32k}, k = 0..5.
    float4 w0[6], w1[6];
    {
        const float4* w0v = reinterpret_cast<const float4*>(w);
        const float4* w1v = reinterpret_cast<const float4*>(w + DQ);
        #pragma unroll
        for (int k = 0; k < 6; k++) {
            w0[k] = w0v[lane + 32 * k];
            w1[k] = w1v[lane + 32 * k];
        }
    }

    // Balanced contiguous stage range for this block.
    const int n_it  = QS + (bid < RS ? 1 : 0);
    const int start = bid * QS + (bid < RS ? bid : RS);

    // Per-thread per-cluster accumulators; lane i (i<8) counts cluster-i rows.
    float acc0[CQ], acc1[CQ];
    #pragma unroll
    for (int i = 0; i < CQ; i++) { acc0[i] = 0.0f; acc1[i] = 0.0f; }
    int my_cnt = 0;
    int cur_b  = start / STAGES_PER_BATCH;

    // Prologue: fill the ring (n_it >= 53 > NSTAGE always).
    if (tid == 0) {
        #pragma unroll
        for (int j = 0; j < NSTAGE; j++) {
            mbar_expect_tx(full_b[j], STAGE_BYTES);
            bulk_g2s(sx_base + j * STAGE_BYTES,
                     x + (size_t)(start + j) * STAGE_ROWS * DQ,
                     STAGE_BYTES, full_b[j]);
        }
    }

    #define FLUSH_WARP(bb)                                                       \
        do {                                                                     \
            _Pragma("unroll")                                                    \
            for (int _i = 0; _i < CQ; _i++) {                                    \
                _Pragma("unroll")                                                \
                for (int _o = 16; _o > 0; _o >>= 1) {                            \
                    acc0[_i] += __shfl_down_sync(0xffffffffu, acc0[_i], _o);     \
                    acc1[_i] += __shfl_down_sync(0xffffffffu, acc1[_i], _o);     \
                }                                                                \
            }                                                                    \
            if (lane == 0) {                                                     \
                _Pragma("unroll")                                                \
                for (int _i = 0; _i < CQ; _i++) {                                \
                    atomicAdd(&s_bins[((bb) * CQ + _i) * 3 + 0], acc0[_i]);      \
                    atomicAdd(&s_bins[((bb) * CQ + _i) * 3 + 1], acc1[_i]);      \
                }                                                                \
            }                                                                    \
            if (lane < CQ && my_cnt > 0)                                         \
                atomicAdd(&s_bins[((bb) * CQ + lane) * 3 + 2], (float)my_cnt);   \
            _Pragma("unroll")                                                    \
            for (int _i = 0; _i < CQ; _i++) { acc0[_i] = 0.0f; acc1[_i] = 0.0f; }\
            my_cnt = 0;                                                          \
        } while (0)

    for (int it = 0; it < n_it; it++) {
        const int slot  = it & (NSTAGE - 1);
        const int stage = start + it;
        const int b     = stage / STAGES_PER_BATCH;   // block-uniform
        if (b != cur_b) { FLUSH_WARP(cur_b); cur_b = b; }

        const int row = stage * STAGE_ROWS + warp;    // this warp's row
        const int c   = labels[row];                  // warp-uniform broadcast

        mbar_wait(full_b[slot], (unsigned)((it >> 2) & 1));

        const float4* rp = s_x + slot * STAGE_F4 + warp * ROW_F4;
        float d0 = 0.0f, d1 = 0.0f;
        #pragma unroll
        for (int k = 0; k < 6; k++) {
            const float4 vv = rp[lane + 32 * k];      // conflict-free LDS.128
            d0 = fmaf(vv.x, w0[k].x, d0); d0 = fmaf(vv.y, w0[k].y, d0);
            d0 = fmaf(vv.z, w0[k].z, d0); d0 = fmaf(vv.w, w0[k].w, d0);
            d1 = fmaf(vv.x, w1[k].x, d1); d1 = fmaf(vv.y, w1[k].y, d1);
            d1 = fmaf(vv.z, w1[k].z, d1); d1 = fmaf(vv.w, w1[k].w, d1);
        }
        #pragma unroll
        for (int i = 0; i < CQ; i++) {
            if (c == i) { acc0[i] += d0; acc1[i] += d1; }
        }
        if (lane == c) my_cnt++;

        mbar_arrive(empty_b[slot]);                   // done reading this slot

        if (tid == 0 && it + NSTAGE < n_it) {
            const int jt = it + NSTAGE;               // same slot as `slot`
            mbar_wait(empty_b[slot], (unsigned)(((jt >> 2) + 1) & 1));
            mbar_expect_tx(full_b[slot], STAGE_BYTES);
            bulk_g2s(sx_base + slot * STAGE_BYTES,
                     x + (size_t)(start + jt) * STAGE_ROWS * DQ,
                     STAGE_BYTES, full_b[slot]);
        }
    }
    FLUSH_WARP(cur_b);
    #undef FLUSH_WARP

    __syncthreads();
    if (tid < BQ * CQ * 3) atomicAdd(&g_accum[tid], s_bins[tid]);
    __threadfence();   // order this block's global atomics before the ticket
    __syncthreads();

    if (tid == 0) {
        unsigned t = atomicAdd(&g_ticket, 1u);
        s_last = (t == (unsigned)(GRID - 1)) ? 1 : 0;
    }
    __syncthreads();
    if (!s_last) return;

    // ---- last block: finalize ----
    __threadfence();
    float bl0 = 0.0f, bl1 = 0.0f;
    const bool isb = (tid < BQ);
    if (isb) {
        const float b0 = hb[0], b1 = hb[1];
        float best = -FLT_MAX;
        #pragma unroll
        for (int c = 0; c < CQ; c++) {
            const float s0 = __ldcg(&g_accum[(tid * CQ + c) * 3 + 0]);
            const float s1 = __ldcg(&g_accum[(tid * CQ + c) * 3 + 1]);
            const float cn = __ldcg(&g_accum[(tid * CQ + c) * 3 + 2]);
            const float inv = 1.0f / fmaxf(cn, 1.0f);
            const float l0 = s0 * inv + b0;
            const float l1 = s1 * inv + b1;
            // NC=2: 1 - softmax(l)[0] = sigmoid(l1 - l0), monotone in (l1 - l0).
            const float score = l1 - l0;
            if (score > best) { best = score; bl0 = l0; bl1 = l1; }
        }
    }
    __syncthreads();   // all reads of g_accum done before reset
    if (tid < BQ * CQ * 3) g_accum[tid] = 0.0f;   // self-reset for next replay
    if (tid == 0) g_ticket = 0u;
    if (isb) {
        out[tid * NCQ + 0] = bl0;
        out[tid * NCQ + 1] = bl1;
    }
}

extern "C" void kernel_launch(void* const* d_in, const int* in_sizes, int n_in,
                              void* d_out, int out_size)
{
    const float* x      = (const float*)d_in[0]; // inst_feat [8,16384,768] f32
    const int*   labels = (const int*)  d_in[1]; // [8,16384] i32
    const float* w      = (const float*)d_in[2]; // head_w [2,768] f32
    const float* hb     = (const float*)d_in[3]; // head_b [2] f32
    float* out = (float*)d_out;                  // [8,2] f32

    cudaFuncSetAttribute(fused_kernel,
                         cudaFuncAttributeMaxDynamicSharedMemorySize,
                         NSTAGE * STAGE_BYTES);
    fused_kernel<<<GRID, THREADS, NSTAGE * STAGE_BYTES>>>(x, labels, w, hb, out);
}